// round 12
// baseline (speedup 1.0000x reference)
#include <cuda_runtime.h>
#include <cuda_bf16.h>
#include <cuda_fp16.h>
#include <cstdint>

#define N_NODES   50000
#define N_PAD     50048          // 391 * 128
#define DEG       16
#define IN_F      256
#define OUT_C     256            // NUM_HEADS * OUT_FEATS
#define NUM_HEADS 4
#define OUT_F     64
#define NEG_SLOPE 0.2f

// ---------------- scratch (static device globals; no allocation) ------------
__device__ float  g_wt[(size_t)OUT_C * IN_F];           // W^T [n][k], tf32-rounded
__device__ __half g_hh[(size_t)N_PAD * OUT_C];          // projected features (fp16)
__device__ float  g_sl[(size_t)N_PAD * NUM_HEADS];      // dst scores (fp32)
__device__ float  g_sr[(size_t)N_PAD * NUM_HEADS];      // src scores (fp32)

__device__ __forceinline__ uint32_t smem_u32(const void* p) {
    uint32_t a;
    asm("{ .reg .u64 t; cvta.to.shared.u64 t, %1; cvt.u32.u64 %0, t; }" : "=r"(a) : "l"(p));
    return a;
}

__device__ __forceinline__ void ldsm_x4(uint32_t* f, uint32_t addr) {
    asm volatile("ldmatrix.sync.aligned.m8n8.x4.shared.b16 {%0,%1,%2,%3}, [%4];"
                 : "=r"(f[0]), "=r"(f[1]), "=r"(f[2]), "=r"(f[3]) : "r"(addr));
}

__device__ __forceinline__ void mma_tf32(float* c, const uint32_t* a,
                                         uint32_t b0, uint32_t b1) {
    asm volatile("mma.sync.aligned.m16n8k8.row.col.f32.tf32.tf32.f32 "
                 "{%0,%1,%2,%3}, {%4,%5,%6,%7}, {%8,%9}, {%0,%1,%2,%3};"
                 : "+f"(c[0]), "+f"(c[1]), "+f"(c[2]), "+f"(c[3])
                 : "r"(a[0]), "r"(a[1]), "r"(a[2]), "r"(a[3]), "r"(b0), "r"(b1));
}

__device__ __forceinline__ float to_tf32(float x) {
    uint32_t u;
    asm("cvt.rna.tf32.f32 %0, %1;" : "=r"(u) : "f"(x));
    return __uint_as_float(u);
}

// ---------------------------------------------------------------------------
// Kernel B: transpose W [k][n] -> g_wt [n][k], tf32-rounded (256KB, ~4us)
// ---------------------------------------------------------------------------
__global__ __launch_bounds__(256) void gat_transpose_w(const float* __restrict__ W)
{
    __shared__ float tile[32][33];
    const int bk = blockIdx.x * 32;
    const int bn = blockIdx.y * 32;
    const int tx = threadIdx.x & 31;
    const int ty = threadIdx.x >> 5;
    #pragma unroll
    for (int j = 0; j < 32; j += 8)
        tile[ty + j][tx] = W[(size_t)(bk + ty + j) * OUT_C + bn + tx];
    __syncthreads();
    #pragma unroll
    for (int j = 0; j < 32; j += 8)
        g_wt[(size_t)(bn + ty + j) * IN_F + bk + tx] = to_tf32(tile[tx][ty + j]);
}

// ---------------------------------------------------------------------------
// Kernel C (round-6 proven mainloop): 1xTF32 mma.sync GEMM h = feat @ W.
// Grid is (2, 391) with bn = blockIdx.x so the two CTAs sharing an A tile
// are launch-adjacent (same wave) -> A's second read hits L2.
// CTA = 128(M) x 128(N); 8 warps 2(m) x 4(n); k-chunk 32; 2 CTAs/SM.
// Epilogue: h stored as FP16 + fused fp32 attn score dots.
// ---------------------------------------------------------------------------
#define ASTR 36

__global__ __launch_bounds__(256, 2) void gat_mma_kernel(
    const float* __restrict__ feat,
    const float* __restrict__ attn_l,
    const float* __restrict__ attn_r,
    int M)
{
    __shared__ __align__(16) float sA[128 * ASTR];
    __shared__ __align__(16) float sB[128 * ASTR];
    __shared__ float s_sl[128][2][2];
    __shared__ float s_sr[128][2][2];

    const int tid  = threadIdx.x;
    const int wid  = tid >> 5;
    const int lane = tid & 31;
    const int bm   = blockIdx.y * 128;     // swapped: bn varies fastest
    const int bn   = blockIdx.x * 128;
    const int wm   = wid >> 2;
    const int wn   = wid & 3;

    const uint32_t sA_b = smem_u32(sA);
    const uint32_t sB_b = smem_u32(sB);

    float acc[4][4][4];
    #pragma unroll
    for (int mt = 0; mt < 4; mt++)
        #pragma unroll
        for (int nt = 0; nt < 4; nt++)
            #pragma unroll
            for (int r = 0; r < 4; r++) acc[mt][nt][r] = 0.f;

    const int lrow = tid >> 1;
    const int lcol = (tid & 1) * 16;
    const bool arow_ok = (bm + lrow) < M;
    const float* aptr = feat + (size_t)(bm + lrow) * IN_F + lcol;
    const float* bptr = g_wt + (size_t)(bn + lrow) * IN_F + lcol;
    float* const sA_st = sA + lrow * ASTR + lcol;
    float* const sB_st = sB + lrow * ASTR + lcol;

    const int mi  = lane >> 3;
    const int aro = ((mi & 1) << 3) + (lane & 7);
    const int aco = (mi >> 1) << 2;
    const int bro = ((mi >> 1) << 3) + (lane & 7);
    const int bco = (mi & 1) << 2;

    for (int c = 0; c < 8; c++) {
        __syncthreads();
        {
            float4 a0, a1, a2, a3;
            if (arow_ok) {
                a0 = *reinterpret_cast<const float4*>(aptr + c * 32);
                a1 = *reinterpret_cast<const float4*>(aptr + c * 32 + 4);
                a2 = *reinterpret_cast<const float4*>(aptr + c * 32 + 8);
                a3 = *reinterpret_cast<const float4*>(aptr + c * 32 + 12);
            } else {
                a0 = a1 = a2 = a3 = make_float4(0.f, 0.f, 0.f, 0.f);
            }
            float4 b0 = *reinterpret_cast<const float4*>(bptr + c * 32);
            float4 b1 = *reinterpret_cast<const float4*>(bptr + c * 32 + 4);
            float4 b2 = *reinterpret_cast<const float4*>(bptr + c * 32 + 8);
            float4 b3 = *reinterpret_cast<const float4*>(bptr + c * 32 + 12);
            *reinterpret_cast<float4*>(sA_st)      = make_float4(to_tf32(a0.x), to_tf32(a0.y), to_tf32(a0.z), to_tf32(a0.w));
            *reinterpret_cast<float4*>(sA_st + 4)  = make_float4(to_tf32(a1.x), to_tf32(a1.y), to_tf32(a1.z), to_tf32(a1.w));
            *reinterpret_cast<float4*>(sA_st + 8)  = make_float4(to_tf32(a2.x), to_tf32(a2.y), to_tf32(a2.z), to_tf32(a2.w));
            *reinterpret_cast<float4*>(sA_st + 12) = make_float4(to_tf32(a3.x), to_tf32(a3.y), to_tf32(a3.z), to_tf32(a3.w));
            *reinterpret_cast<float4*>(sB_st)      = b0;
            *reinterpret_cast<float4*>(sB_st + 4)  = b1;
            *reinterpret_cast<float4*>(sB_st + 8)  = b2;
            *reinterpret_cast<float4*>(sB_st + 12) = b3;
        }
        __syncthreads();

        #pragma unroll
        for (int ks = 0; ks < 4; ks++) {
            uint32_t af[4][4];
            uint32_t bf[2][4];
            #pragma unroll
            for (int bp = 0; bp < 2; bp++) {
                int r = wn * 32 + bp * 16 + bro;
                uint32_t off = (uint32_t)(r * ASTR + ks * 8 + bco) * 4;
                ldsm_x4(bf[bp], sB_b + off);
            }
            #pragma unroll
            for (int mt = 0; mt < 4; mt++) {
                int r = wm * 64 + mt * 16 + aro;
                uint32_t off = (uint32_t)(r * ASTR + ks * 8 + aco) * 4;
                ldsm_x4(af[mt], sA_b + off);
            }
            #pragma unroll
            for (int mt = 0; mt < 4; mt++)
                #pragma unroll
                for (int nt = 0; nt < 4; nt++)
                    mma_tf32(acc[mt][nt], af[mt],
                             bf[nt >> 1][(nt & 1) * 2],
                             bf[nt >> 1][(nt & 1) * 2 + 1]);
        }
    }

    // ---- epilogue: store h as fp16 + fused fp32 score dots ------------------
    const int hdl = wn >> 1;
    const int wp  = wn & 1;

    float alv[4][2], arv[4][2];
    #pragma unroll
    for (int nt = 0; nt < 4; nt++) {
        int col = bn + wn * 32 + nt * 8 + (lane & 3) * 2;
        alv[nt][0] = attn_l[col];     alv[nt][1] = attn_l[col + 1];
        arv[nt][0] = attn_r[col];     arv[nt][1] = attn_r[col + 1];
    }

    #pragma unroll
    for (int mt = 0; mt < 4; mt++) {
        int r0 = wm * 64 + mt * 16 + (lane >> 2);
        int r8 = r0 + 8;
        float sl0 = 0.f, sl8 = 0.f, sr0 = 0.f, sr8 = 0.f;
        #pragma unroll
        for (int nt = 0; nt < 4; nt++) {
            int col = bn + wn * 32 + nt * 8 + (lane & 3) * 2;
            float2 v0 = make_float2(acc[mt][nt][0], acc[mt][nt][1]);
            float2 v8 = make_float2(acc[mt][nt][2], acc[mt][nt][3]);
            __half2 p0 = __floats2half2_rn(v0.x, v0.y);
            __half2 p8 = __floats2half2_rn(v8.x, v8.y);
            *reinterpret_cast<__half2*>(&g_hh[(size_t)(bm + r0) * OUT_C + col]) = p0;
            *reinterpret_cast<__half2*>(&g_hh[(size_t)(bm + r8) * OUT_C + col]) = p8;
            sl0 += alv[nt][0] * v0.x + alv[nt][1] * v0.y;
            sl8 += alv[nt][0] * v8.x + alv[nt][1] * v8.y;
            sr0 += arv[nt][0] * v0.x + arv[nt][1] * v0.y;
            sr8 += arv[nt][0] * v8.x + arv[nt][1] * v8.y;
        }
        #pragma unroll
        for (int off = 1; off < 4; off <<= 1) {
            sl0 += __shfl_xor_sync(0xffffffffu, sl0, off);
            sl8 += __shfl_xor_sync(0xffffffffu, sl8, off);
            sr0 += __shfl_xor_sync(0xffffffffu, sr0, off);
            sr8 += __shfl_xor_sync(0xffffffffu, sr8, off);
        }
        if ((lane & 3) == 0) {
            s_sl[r0][hdl][wp] = sl0;  s_sl[r8][hdl][wp] = sl8;
            s_sr[r0][hdl][wp] = sr0;  s_sr[r8][hdl][wp] = sr8;
        }
    }
    __syncthreads();

    if (tid < 128) {
        int gr = bm + tid;
        int hb = bn >> 6;
        g_sl[(size_t)gr * 4 + hb + 0] = s_sl[tid][0][0] + s_sl[tid][0][1];
        g_sl[(size_t)gr * 4 + hb + 1] = s_sl[tid][1][0] + s_sl[tid][1][1];
        g_sr[(size_t)gr * 4 + hb + 0] = s_sr[tid][0][0] + s_sr[tid][0][1];
        g_sr[(size_t)gr * 4 + hb + 1] = s_sr[tid][1][0] + s_sr[tid][1][1];
    }
}

// ---------------------------------------------------------------------------
// Kernel D: softmax + fp16 aggregation; ONE WARP PER NODE (8 nodes/block).
// Lane l owns output features 8l..8l+7, gathered as one uint4 (16B) per edge
// -> half the LDG instructions of the 64-thread variant, same coalescing.
// Edge indices broadcast via shfl; alpha via smem.
// ---------------------------------------------------------------------------
__global__ __launch_bounds__(256) void gat_agg_kernel(
    const int*    __restrict__ col_ind,
    const uint4*  __restrict__ hh4,    // g_hh viewed as [N][32] x (8 halves)
    const float4* __restrict__ sl4,
    const float4* __restrict__ sr4,
    float2*       __restrict__ out2)   // out viewed as [N][128] float2
{
    const int w    = threadIdx.x >> 5;           // node within block (0..7)
    const int lane = threadIdx.x & 31;
    const int n    = blockIdx.x * 8 + w;

    __shared__ float salpha[8][16][4];

    int s = 0;
    if (lane < 16) s = col_ind[n * DEG + lane];

    if (lane < 16) {
        float4 l = sl4[n];
        float4 r = sr4[s];
        float e0 = l.x + r.x, e1 = l.y + r.y, e2 = l.z + r.z, e3 = l.w + r.w;
        e0 = (e0 > 0.f) ? e0 : NEG_SLOPE * e0;
        e1 = (e1 > 0.f) ? e1 : NEG_SLOPE * e1;
        e2 = (e2 > 0.f) ? e2 : NEG_SLOPE * e2;
        e3 = (e3 > 0.f) ? e3 : NEG_SLOPE * e3;
        float m0 = e0, m1 = e1, m2 = e2, m3 = e3;
        #pragma unroll
        for (int off = 8; off > 0; off >>= 1) {
            m0 = fmaxf(m0, __shfl_xor_sync(0xffffu, m0, off));
            m1 = fmaxf(m1, __shfl_xor_sync(0xffffu, m1, off));
            m2 = fmaxf(m2, __shfl_xor_sync(0xffffu, m2, off));
            m3 = fmaxf(m3, __shfl_xor_sync(0xffffu, m3, off));
        }
        float x0 = __expf(e0 - m0), x1 = __expf(e1 - m1);
        float x2 = __expf(e2 - m2), x3 = __expf(e3 - m3);
        float s0 = x0, s1 = x1, s2 = x2, s3 = x3;
        #pragma unroll
        for (int off = 8; off > 0; off >>= 1) {
            s0 += __shfl_xor_sync(0xffffu, s0, off);
            s1 += __shfl_xor_sync(0xffffu, s1, off);
            s2 += __shfl_xor_sync(0xffffu, s2, off);
            s3 += __shfl_xor_sync(0xffffu, s3, off);
        }
        *reinterpret_cast<float4*>(&salpha[w][lane][0]) =
            make_float4(x0 / s0, x1 / s1, x2 / s2, x3 / s3);
    }
    __syncwarp();

    // lane owns 8 features: 8*lane .. 8*lane+7 ; head = lane/8
    const int hd = lane >> 3;
    float acc[8];
    #pragma unroll
    for (int i = 0; i < 8; i++) acc[i] = 0.f;

    #pragma unroll
    for (int k = 0; k < DEG; k++) {
        int sk = __shfl_sync(0xffffffffu, s, k);
        float a = salpha[w][k][hd];
        uint4 u = hh4[(size_t)sk * 32 + lane];
        float2 f0 = __half22float2(*reinterpret_cast<__half2*>(&u.x));
        float2 f1 = __half22float2(*reinterpret_cast<__half2*>(&u.y));
        float2 f2 = __half22float2(*reinterpret_cast<__half2*>(&u.z));
        float2 f3 = __half22float2(*reinterpret_cast<__half2*>(&u.w));
        acc[0] += a * f0.x;  acc[1] += a * f0.y;
        acc[2] += a * f1.x;  acc[3] += a * f1.y;
        acc[4] += a * f2.x;  acc[5] += a * f2.y;
        acc[6] += a * f3.x;  acc[7] += a * f3.y;
    }

    // write 32B per lane as 4 float2 (coalesced 1KB per node)
    size_t ob = (size_t)n * 128 + lane * 4;
    out2[ob + 0] = make_float2(acc[0], acc[1]);
    out2[ob + 1] = make_float2(acc[2], acc[3]);
    out2[ob + 2] = make_float2(acc[4], acc[5]);
    out2[ob + 3] = make_float2(acc[6], acc[7]);
}

// ---------------------------------------------------------------------------
// Launch. Inputs: row_ptr, col_ind, col_ptr, row_ind, feat, W, attn_l, attn_r
// ---------------------------------------------------------------------------
extern "C" void kernel_launch(void* const* d_in, const int* in_sizes, int n_in,
                              void* d_out, int out_size)
{
    const int*   col_ind = (const int*)  d_in[1];
    const float* feat    = (const float*)d_in[4];
    const float* W       = (const float*)d_in[5];
    const float* attn_l  = (const float*)d_in[6];
    const float* attn_r  = (const float*)d_in[7];
    float*       out     = (float*)      d_out;

    const int M = in_sizes[4] / IN_F;    // 50000

    __half* hh_ptr = nullptr;
    float  *sl_ptr = nullptr, *sr_ptr = nullptr;
    cudaGetSymbolAddress((void**)&hh_ptr, g_hh);
    cudaGetSymbolAddress((void**)&sl_ptr, g_sl);
    cudaGetSymbolAddress((void**)&sr_ptr, g_sr);

    dim3 gtw(IN_F / 32, OUT_C / 32);
    gat_transpose_w<<<gtw, 256>>>(W);

    dim3 gmm(2, N_PAD / 128);            // bn fastest: A-tile pairs adjacent
    gat_mma_kernel<<<gmm, 256>>>(feat, attn_l, attn_r, M);

    gat_agg_kernel<<<M / 8, 256>>>(col_ind,
                                   (const uint4*)hh_ptr,
                                   (const float4*)sl_ptr,
                                   (const float4*)sr_ptr,
                                   (float2*)out);
}